// round 1
// baseline (speedup 1.0000x reference)
#include <cuda_runtime.h>
#include <math_constants.h>

#define NB 4
#define NT 4096
#define NC 2048
#define ND 128
#define NM (NB * NT)

// Scratch (device globals: allocation-free per harness rules)
// g_qT/g_kT: [B][D][T] (d-major, so attention smem tiles load with zero transpose)
// g_v:       [B][T][D] (row-major)
__device__ float g_qT[(size_t)NB * ND * NT];
__device__ float g_kT[(size_t)NB * ND * NT];
__device__ float g_v [(size_t)NB * NT * ND];

// ---------------------------------------------------------------------------
// Projection: out = x @ W for W in {Wq, Wk, Wv}, selected by blockIdx.z.
// Classic 128x128 tile, BK=16, 256 threads, 8x8 per-thread microtile.
// ---------------------------------------------------------------------------
__global__ __launch_bounds__(256, 2) void proj_kernel(
    const float* __restrict__ x, const float* __restrict__ Wq,
    const float* __restrict__ Wk, const float* __restrict__ Wv)
{
    const int z = blockIdx.z;
    const float* __restrict__ W = (z == 0) ? Wq : (z == 1) ? Wk : Wv;

    __shared__ float As[16][132];  // [k][m], stride 132 => float4-aligned rows
    __shared__ float Bs[16][128];  // [k][n]

    const int m0 = blockIdx.x * 128;
    const int tid = threadIdx.x;
    const int tx = tid & 15, ty = tid >> 4;

    float acc[8][8] = {};

    for (int k0 = 0; k0 < NC; k0 += 16) {
        // A tile: 128 rows x 16 k, transpose-stored into As[k][m]
#pragma unroll
        for (int h = 0; h < 2; h++) {
            int sidx = tid + h * 256;
            int row = sidx >> 2;
            int seg = (sidx & 3) * 4;
            float4 a = *(const float4*)&x[(size_t)(m0 + row) * NC + k0 + seg];
            As[seg + 0][row] = a.x;
            As[seg + 1][row] = a.y;
            As[seg + 2][row] = a.z;
            As[seg + 3][row] = a.w;
        }
        // B tile: 16 k x 128 n, direct
#pragma unroll
        for (int h = 0; h < 2; h++) {
            int sidx = tid + h * 256;
            int row = sidx >> 5;
            int col = (sidx & 31) * 4;
            *(float4*)&Bs[row][col] = *(const float4*)&W[(size_t)(k0 + row) * ND + col];
        }
        __syncthreads();

#pragma unroll
        for (int k = 0; k < 16; k++) {
            float a[8], b[8];
            *(float4*)&a[0] = *(const float4*)&As[k][ty * 8];
            *(float4*)&a[4] = *(const float4*)&As[k][ty * 8 + 4];
            *(float4*)&b[0] = *(const float4*)&Bs[k][tx * 8];
            *(float4*)&b[4] = *(const float4*)&Bs[k][tx * 8 + 4];
#pragma unroll
            for (int i = 0; i < 8; i++)
#pragma unroll
                for (int j = 0; j < 8; j++)
                    acc[i][j] += a[i] * b[j];
        }
        __syncthreads();
    }

    if (z == 2) {
        // V: row-major [B*T][D]
#pragma unroll
        for (int i = 0; i < 8; i++) {
            int row = m0 + ty * 8 + i;
            float4 v0 = make_float4(acc[i][0], acc[i][1], acc[i][2], acc[i][3]);
            float4 v1 = make_float4(acc[i][4], acc[i][5], acc[i][6], acc[i][7]);
            *(float4*)&g_v[(size_t)row * ND + tx * 8] = v0;
            *(float4*)&g_v[(size_t)row * ND + tx * 8 + 4] = v1;
        }
    } else {
        // Q/K: transposed [B][D][T] (scatter; ~8us total extra traffic, fine)
        float* __restrict__ g = (z == 0) ? g_qT : g_kT;
#pragma unroll
        for (int i = 0; i < 8; i++) {
            int row = m0 + ty * 8 + i;
            int bb = row >> 12;            // / NT
            int t = row & (NT - 1);
#pragma unroll
            for (int j = 0; j < 8; j++) {
                int col = tx * 8 + j;
                g[(size_t)(bb * ND + col) * NT + t] = acc[i][j];
            }
        }
    }
}

// ---------------------------------------------------------------------------
// Flash attention, fp32, causal. BQ = BKV = 64, 256 threads.
// Thread (tx,ty in 16x16): S microtile rows ty*4..+3, cols tx*4..+3;
// O microtile rows ty*4..+3, cols tx*8..+7.
// Smem strides chosen so all float4 accesses are 16B-aligned & conflict-free.
// ---------------------------------------------------------------------------
#define SQS 68   // Qs/Ks row stride (d-major [128][SQS])
#define SPS 67   // Ps row stride    (j-major [64][SPS])

__global__ __launch_bounds__(256, 1) void attn_kernel(float* __restrict__ out)
{
    extern __shared__ float sm[];
    float* Qs = sm;                  // [128][SQS]  Qs[d][r]
    float* Ks = Qs + 128 * SQS;      // [128][SQS]  Ks[d][c]
    float* Vs = Ks + 128 * SQS;      // [64][128]   Vs[j][d]
    float* Ps = Vs + 64 * 128;       // [64][SPS]   Ps[j][r]

    const int b  = blockIdx.y;
    const int qb = blockIdx.x;
    const int q0 = qb * 64;
    const int tid = threadIdx.x;
    const int tx = tid & 15, ty = tid >> 4;
    const float scale = 0.08838834764831845f;  // 1/sqrt(128)

    // Load Q tile (64 cols of d-major global): fully coalesced, no transpose
    const float* __restrict__ qbase = g_qT + (size_t)b * ND * NT + q0;
#pragma unroll
    for (int h = 0; h < 8; h++) {
        int sidx = tid + h * 256;
        int d = sidx >> 4;
        int c = (sidx & 15) * 4;
        *(float4*)&Qs[d * SQS + c] = *(const float4*)&qbase[(size_t)d * NT + c];
    }

    float m_i[4], l_i[4], O[4][8];
#pragma unroll
    for (int i = 0; i < 4; i++) {
        m_i[i] = -CUDART_INF_F;
        l_i[i] = 0.f;
#pragma unroll
        for (int c = 0; c < 8; c++) O[i][c] = 0.f;
    }

    const int nTiles = qb + 1;
    for (int jt = 0; jt < nTiles; jt++) {
        const int j0 = jt * 64;

        // K tile
        const float* __restrict__ kbase = g_kT + (size_t)b * ND * NT + j0;
#pragma unroll
        for (int h = 0; h < 8; h++) {
            int sidx = tid + h * 256;
            int d = sidx >> 4;
            int c = (sidx & 15) * 4;
            *(float4*)&Ks[d * SQS + c] = *(const float4*)&kbase[(size_t)d * NT + c];
        }
        __syncthreads();  // Ks (and first-iter Qs) visible; prev O-compute done

        // S = Q @ K^T  (4x4 per thread)
        float S[4][4] = {};
#pragma unroll 4
        for (int d = 0; d < 128; d++) {
            float4 qf = *(const float4*)&Qs[d * SQS + ty * 4];
            float4 kf = *(const float4*)&Ks[d * SQS + tx * 4];
            S[0][0] += qf.x * kf.x; S[0][1] += qf.x * kf.y; S[0][2] += qf.x * kf.z; S[0][3] += qf.x * kf.w;
            S[1][0] += qf.y * kf.x; S[1][1] += qf.y * kf.y; S[1][2] += qf.y * kf.z; S[1][3] += qf.y * kf.w;
            S[2][0] += qf.z * kf.x; S[2][1] += qf.z * kf.y; S[2][2] += qf.z * kf.z; S[2][3] += qf.z * kf.w;
            S[3][0] += qf.w * kf.x; S[3][1] += qf.w * kf.y; S[3][2] += qf.w * kf.z; S[3][3] += qf.w * kf.w;
        }

        // Online softmax (per-row over 16 tx lanes)
        const bool diag = (jt == qb);
#pragma unroll
        for (int i = 0; i < 4; i++) {
            float mt = -CUDART_INF_F;
#pragma unroll
            for (int j = 0; j < 4; j++) {
                float s = S[i][j] * scale;
                if (diag && (tx * 4 + j > ty * 4 + i)) s = -CUDART_INF_F;
                S[i][j] = s;
                mt = fmaxf(mt, s);
            }
#pragma unroll
            for (int off = 8; off >= 1; off >>= 1)
                mt = fmaxf(mt, __shfl_xor_sync(0xffffffffu, mt, off, 16));
            float mnew = fmaxf(m_i[i], mt);
            float alpha = __expf(m_i[i] - mnew);  // exp(-inf)=0 on first tile
            m_i[i] = mnew;
            float rs = 0.f;
#pragma unroll
            for (int j = 0; j < 4; j++) {
                float p = __expf(S[i][j] - mnew);  // exp(-inf)=0 for masked
                S[i][j] = p;
                rs += p;
            }
#pragma unroll
            for (int off = 8; off >= 1; off >>= 1)
                rs += __shfl_xor_sync(0xffffffffu, rs, off, 16);
            l_i[i] = l_i[i] * alpha + rs;
#pragma unroll
            for (int c = 0; c < 8; c++) O[i][c] *= alpha;
            // stash P transposed: Ps[j][r]
#pragma unroll
            for (int j = 0; j < 4; j++)
                Ps[(tx * 4 + j) * SPS + ty * 4 + i] = S[i][j];
        }
        __syncthreads();  // Ps complete; prev Vs reads complete

        // V tile
        const float* __restrict__ vbase = g_v + ((size_t)b * NT + j0) * ND;
#pragma unroll
        for (int h = 0; h < 8; h++) {
            int sidx = tid + h * 256;
            int r = sidx >> 5;
            int c = (sidx & 31) * 4;
            *(float4*)&Vs[r * ND + c] = *(const float4*)&vbase[(size_t)r * ND + c];
        }
        __syncthreads();  // Vs visible

        // O += P @ V  (4 rows x 8 cols per thread)
#pragma unroll 2
        for (int j = 0; j < 64; j++) {
            float pp[4];
            pp[0] = Ps[j * SPS + ty * 4 + 0];
            pp[1] = Ps[j * SPS + ty * 4 + 1];
            pp[2] = Ps[j * SPS + ty * 4 + 2];
            pp[3] = Ps[j * SPS + ty * 4 + 3];
            float4 v0 = *(const float4*)&Vs[j * ND + tx * 8];
            float4 v1 = *(const float4*)&Vs[j * ND + tx * 8 + 4];
            float vv[8] = {v0.x, v0.y, v0.z, v0.w, v1.x, v1.y, v1.z, v1.w};
#pragma unroll
            for (int i = 0; i < 4; i++)
#pragma unroll
                for (int c = 0; c < 8; c++)
                    O[i][c] += pp[i] * vv[c];
        }
        // next-iter top sync protects Ps/Vs reuse
    }

    // Epilogue: normalize and write out [B][T][D]
    float* __restrict__ obase = out + ((size_t)b * NT + q0) * ND;
#pragma unroll
    for (int i = 0; i < 4; i++) {
        float inv = 1.0f / l_i[i];
        float4 v0 = make_float4(O[i][0] * inv, O[i][1] * inv, O[i][2] * inv, O[i][3] * inv);
        float4 v1 = make_float4(O[i][4] * inv, O[i][5] * inv, O[i][6] * inv, O[i][7] * inv);
        *(float4*)&obase[(size_t)(ty * 4 + i) * ND + tx * 8] = v0;
        *(float4*)&obase[(size_t)(ty * 4 + i) * ND + tx * 8 + 4] = v1;
    }
}

// ---------------------------------------------------------------------------
extern "C" void kernel_launch(void* const* d_in, const int* in_sizes, int n_in,
                              void* d_out, int out_size)
{
    const float* x  = (const float*)d_in[0];
    const float* Wq = (const float*)d_in[1];
    const float* Wk = (const float*)d_in[2];
    const float* Wv = (const float*)d_in[3];
    float* out = (float*)d_out;

    const size_t smem_bytes =
        (size_t)(128 * SQS + 128 * SQS + 64 * 128 + 64 * SPS) * sizeof(float);  // 119552
    cudaFuncSetAttribute(attn_kernel,
                         cudaFuncAttributeMaxDynamicSharedMemorySize,
                         (int)smem_bytes);

    dim3 pgrid(NM / 128, 1, 3);
    proj_kernel<<<pgrid, 256>>>(x, Wq, Wk, Wv);

    dim3 agrid(NT / 64, NB);
    attn_kernel<<<agrid, 256, smem_bytes>>>(out);
}

// round 4
// speedup vs baseline: 1.6849x; 1.6849x over previous
#include <cuda_runtime.h>
#include <cuda_bf16.h>
#include <math_constants.h>
#include <cstdint>

#define NB 4
#define NT 4096
#define NC 2048
#define ND 128
#define NM (NB * NT)

// ---------------------------------------------------------------------------
// Scratch (device globals: allocation-free per harness rules)
// ---------------------------------------------------------------------------
__device__ float g_qT[(size_t)NB * ND * NT];   // [B][D][T] d-major
__device__ float g_kT[(size_t)NB * ND * NT];   // [B][D][T] d-major
__device__ float g_v [(size_t)NB * NT * ND];   // [B][T][D]

__device__ __nv_bfloat16 g_xh[(size_t)NM * NC];   // x split hi  [M][K]
__device__ __nv_bfloat16 g_xl[(size_t)NM * NC];   // x split lo  [M][K]
__device__ __nv_bfloat16 g_wh[3 * ND * NC];       // W^T split hi [z][N][K]
__device__ __nv_bfloat16 g_wl[3 * ND * NC];       // W^T split lo [z][N][K]

// ---------------------------------------------------------------------------
// sm_80+ PTX helpers (NO sm_100a-only instructions; harness targets sm_100)
// ---------------------------------------------------------------------------
__device__ __forceinline__ uint32_t smem_u32(const void* p) {
    uint32_t a;
    asm("{ .reg .u64 t; cvta.to.shared.u64 t, %1; cvt.u32.u64 %0, t; }"
        : "=r"(a) : "l"(p));
    return a;
}

__device__ __forceinline__ void ldsm_x4(uint32_t* r, uint32_t addr) {
    asm volatile("ldmatrix.sync.aligned.m8n8.x4.shared.b16 {%0,%1,%2,%3}, [%4];"
                 : "=r"(r[0]), "=r"(r[1]), "=r"(r[2]), "=r"(r[3])
                 : "r"(addr));
}

// D(16x8,f32) += A(16x16,bf16 row) * B(16x8,bf16 col)
__device__ __forceinline__ void mma_bf16(float* c, const uint32_t* a,
                                         const uint32_t* b) {
    asm volatile(
        "mma.sync.aligned.m16n8k16.row.col.f32.bf16.bf16.f32 "
        "{%0,%1,%2,%3}, {%4,%5,%6,%7}, {%8,%9}, {%0,%1,%2,%3};"
        : "+f"(c[0]), "+f"(c[1]), "+f"(c[2]), "+f"(c[3])
        : "r"(a[0]), "r"(a[1]), "r"(a[2]), "r"(a[3]), "r"(b[0]), "r"(b[1]));
}

#define CP_ASYNC16(smem_addr, gptr) \
    asm volatile("cp.async.cg.shared.global [%0], [%1], 16;" \
                 :: "r"(smem_addr), "l"(gptr) : "memory")
#define CP_COMMIT() asm volatile("cp.async.commit_group;" ::: "memory")
#define CP_WAIT1()  asm volatile("cp.async.wait_group 1;" ::: "memory")

// ---------------------------------------------------------------------------
// Prep: split fp32 -> hi/lo bf16 (x row-major; W transposed to [N][K])
// ---------------------------------------------------------------------------
__global__ __launch_bounds__(256) void split_x_kernel(const float* __restrict__ x) {
    size_t i = ((size_t)blockIdx.x * 256 + threadIdx.x) * 8;
    float4 a = *(const float4*)(x + i);
    float4 b = *(const float4*)(x + i + 4);
    float v[8] = {a.x, a.y, a.z, a.w, b.x, b.y, b.z, b.w};
    __nv_bfloat16 h[8], l[8];
#pragma unroll
    for (int j = 0; j < 8; j++) {
        h[j] = __float2bfloat16(v[j]);
        l[j] = __float2bfloat16(v[j] - __bfloat162float(h[j]));
    }
    *(uint4*)(g_xh + i) = *(const uint4*)h;
    *(uint4*)(g_xl + i) = *(const uint4*)l;
}

__global__ __launch_bounds__(256) void split_w_kernel(
    const float* __restrict__ Wq, const float* __restrict__ Wk,
    const float* __restrict__ Wv) {
    const int z = blockIdx.y;
    const float* __restrict__ W = (z == 0) ? Wq : (z == 1) ? Wk : Wv;
    int idx = blockIdx.x * 256 + threadIdx.x;   // 0 .. 128*2048-1
    int k = idx & (NC - 1);
    int n = idx >> 11;
    float v = W[(size_t)k * ND + n];
    __nv_bfloat16 h = __float2bfloat16(v);
    __nv_bfloat16 l = __float2bfloat16(v - __bfloat162float(h));
    size_t o = (size_t)z * ND * NC + (size_t)n * NC + k;
    g_wh[o] = h;
    g_wl[o] = l;
}

// ---------------------------------------------------------------------------
// Projection via mma.sync: C[128x128] = X @ W, split-bf16 (hh + lh + hl).
// 256 threads (8 warps); warp w owns rows 16w..16w+15, all 128 cols.
// KC=32, 3-stage cp.async pipeline. Smem rows: 64B data + 16B pad (80B) so
// ldmatrix 8-row groups hit distinct banks (0,20,8,28,16,4,24,12).
// ---------------------------------------------------------------------------
#define KC 32
#define ROWB 80
#define MATB (128 * ROWB)        // 10240 per matrix tile
#define STAGEB (4 * MATB)        // Xh, Xl, Wh, Wl
#define NSTAGE 3
#define NCHUNK (NC / KC)         // 64

__global__ __launch_bounds__(256) void proj_mma_kernel() {
    extern __shared__ char psm[];
    const uint32_t sb = smem_u32(psm);
    const int tid = threadIdx.x;
    const int w = tid >> 5;
    const int l = tid & 31;
    const int z = blockIdx.z;
    const int m0 = blockIdx.x * 128;

    const char* gb0 = (const char*)(g_xh + (size_t)m0 * NC);
    const char* gb1 = (const char*)(g_xl + (size_t)m0 * NC);
    const char* gb2 = (const char*)(g_wh + (size_t)z * ND * NC);
    const char* gb3 = (const char*)(g_wl + (size_t)z * ND * NC);

    auto load_stage = [&](int st, int c) {
        const size_t k0b = (size_t)c * (KC * 2);
        const char* gb[4] = {gb0 + k0b, gb1 + k0b, gb2 + k0b, gb3 + k0b};
#pragma unroll
        for (int m = 0; m < 4; m++) {
#pragma unroll
            for (int it = 0; it < 2; it++) {
                int q = it * 256 + tid;          // 0..511
                int r = q >> 2;
                int seg = q & 3;
                uint32_t s = sb + st * STAGEB + m * MATB + r * ROWB + seg * 16;
                const char* g = gb[m] + (size_t)r * (NC * 2) + seg * 16;
                CP_ASYNC16(s, g);
            }
        }
    };

    load_stage(0, 0); CP_COMMIT();
    load_stage(1, 1); CP_COMMIT();

    float acc[16][4] = {};

    for (int c = 0; c < NCHUNK; c++) {
        const int st = c % NSTAGE;
        CP_WAIT1();
        __syncthreads();
        if (c + 2 < NCHUNK) { load_stage((c + 2) % NSTAGE, c + 2); CP_COMMIT(); }

        const uint32_t stb = sb + st * STAGEB;
        const uint32_t abase = stb + (w * 16 + (l & 15)) * ROWB + (l >> 4) * 16;
        const uint32_t brow = (l & 7) + ((l >> 4) & 1) * 8;
        const uint32_t bsegl = ((l >> 3) & 1) * 16;

#pragma unroll
        for (int kk = 0; kk < 2; kk++) {
            uint32_t Ah[4], Al[4];
            ldsm_x4(Ah, abase + kk * 32);
            ldsm_x4(Al, abase + kk * 32 + MATB);
#pragma unroll
            for (int jp = 0; jp < 8; jp++) {
                uint32_t bo = stb + 2 * MATB + (16 * jp + brow) * ROWB +
                              kk * 32 + bsegl;
                uint32_t Bh[4], Bl[4];
                ldsm_x4(Bh, bo);
                ldsm_x4(Bl, bo + MATB);
                float* c0 = acc[2 * jp];
                float* c1 = acc[2 * jp + 1];
                mma_bf16(c0, Ah, Bh);     mma_bf16(c1, Ah, Bh + 2);
                mma_bf16(c0, Al, Bh);     mma_bf16(c1, Al, Bh + 2);
                mma_bf16(c0, Ah, Bl);     mma_bf16(c1, Ah, Bl + 2);
            }
        }
    }

    // Epilogue. Fragment mapping: acc[j][0..1] -> row g, cols 8j+2t,+1;
    // acc[j][2..3] -> row g+8. (g = l>>2, t = l&3)
    const int g = l >> 2;
    const int t = l & 3;
    const int row0 = m0 + w * 16 + g;

    if (z == 2) {
        float* __restrict__ o = g_v;
#pragma unroll
        for (int j = 0; j < 16; j++) {
            int col = 8 * j + 2 * t;
            *(float2*)&o[(size_t)row0 * ND + col] =
                make_float2(acc[j][0], acc[j][1]);
            *(float2*)&o[(size_t)(row0 + 8) * ND + col] =
                make_float2(acc[j][2], acc[j][3]);
        }
    } else {
        float* __restrict__ gd = (z == 0) ? g_qT : g_kT;
        const int bb = row0 >> 12;
        const int t0 = row0 & (NT - 1);
#pragma unroll
        for (int j = 0; j < 16; j++) {
            int col = 8 * j + 2 * t;
            gd[(size_t)(bb * ND + col) * NT + t0]           = acc[j][0];
            gd[(size_t)(bb * ND + col + 1) * NT + t0]       = acc[j][1];
            gd[(size_t)(bb * ND + col) * NT + t0 + 8]       = acc[j][2];
            gd[(size_t)(bb * ND + col + 1) * NT + t0 + 8]   = acc[j][3];
        }
    }
}

// ---------------------------------------------------------------------------
// Flash attention, fp32, causal. BQ = BKV = 64, 256 threads.
// Pair scheduling: block handles q-tiles {x, 63-x} -> uniform 65 KV-tiles.
// ---------------------------------------------------------------------------
#define SQS 68
#define SPS 67

__global__ __launch_bounds__(256, 1) void attn_kernel(float* __restrict__ out)
{
    extern __shared__ float sm[];
    float* Qs = sm;                  // [128][SQS]
    float* Ks = Qs + 128 * SQS;      // [128][SQS]
    float* Vs = Ks + 128 * SQS;      // [64][128]
    float* Ps = Vs + 64 * 128;       // [64][SPS]

    const int b  = blockIdx.y;
    const int tid = threadIdx.x;
    const int tx = tid & 15, ty = tid >> 4;
    const float scale = 0.08838834764831845f;  // 1/sqrt(128)

    for (int pass = 0; pass < 2; pass++) {
        const int qb = pass ? (63 - blockIdx.x) : blockIdx.x;
        const int q0 = qb * 64;

        const float* __restrict__ qbase = g_qT + (size_t)b * ND * NT + q0;
#pragma unroll
        for (int h = 0; h < 8; h++) {
            int sidx = tid + h * 256;
            int d = sidx >> 4;
            int c = (sidx & 15) * 4;
            *(float4*)&Qs[d * SQS + c] = *(const float4*)&qbase[(size_t)d * NT + c];
        }

        float m_i[4], l_i[4], O[4][8];
#pragma unroll
        for (int i = 0; i < 4; i++) {
            m_i[i] = -CUDART_INF_F;
            l_i[i] = 0.f;
#pragma unroll
            for (int c = 0; c < 8; c++) O[i][c] = 0.f;
        }

        const int nTiles = qb + 1;
        for (int jt = 0; jt < nTiles; jt++) {
            const int j0 = jt * 64;

            const float* __restrict__ kbase = g_kT + (size_t)b * ND * NT + j0;
#pragma unroll
            for (int h = 0; h < 8; h++) {
                int sidx = tid + h * 256;
                int d = sidx >> 4;
                int c = (sidx & 15) * 4;
                *(float4*)&Ks[d * SQS + c] = *(const float4*)&kbase[(size_t)d * NT + c];
            }
            __syncthreads();

            float S[4][4] = {};
#pragma unroll 4
            for (int d = 0; d < 128; d++) {
                float4 qf = *(const float4*)&Qs[d * SQS + ty * 4];
                float4 kf = *(const float4*)&Ks[d * SQS + tx * 4];
                S[0][0] += qf.x * kf.x; S[0][1] += qf.x * kf.y; S[0][2] += qf.x * kf.z; S[0][3] += qf.x * kf.w;
                S[1][0] += qf.y * kf.x; S[1][1] += qf.y * kf.y; S[1][2] += qf.y * kf.z; S[1][3] += qf.y * kf.w;
                S[2][0] += qf.z * kf.x; S[2][1] += qf.z * kf.y; S[2][2] += qf.z * kf.z; S[2][3] += qf.z * kf.w;
                S[3][0] += qf.w * kf.x; S[3][1] += qf.w * kf.y; S[3][2] += qf.w * kf.z; S[3][3] += qf.w * kf.w;
            }

            const bool diag = (jt == qb);
#pragma unroll
            for (int i = 0; i < 4; i++) {
                float mt = -CUDART_INF_F;
#pragma unroll
                for (int j = 0; j < 4; j++) {
                    float s = S[i][j] * scale;
                    if (diag && (tx * 4 + j > ty * 4 + i)) s = -CUDART_INF_F;
                    S[i][j] = s;
                    mt = fmaxf(mt, s);
                }
#pragma unroll
                for (int off = 8; off >= 1; off >>= 1)
                    mt = fmaxf(mt, __shfl_xor_sync(0xffffffffu, mt, off, 16));
                float mnew = fmaxf(m_i[i], mt);
                float alpha = __expf(m_i[i] - mnew);
                m_i[i] = mnew;
                float rs = 0.f;
#pragma unroll
                for (int j = 0; j < 4; j++) {
                    float p = __expf(S[i][j] - mnew);
                    S[i][j] = p;
                    rs += p;
                }
#pragma unroll
                for (int off = 8; off >= 1; off >>= 1)
                    rs += __shfl_xor_sync(0xffffffffu, rs, off, 16);
                l_i[i] = l_i[i] * alpha + rs;
#pragma unroll
                for (int c = 0; c < 8; c++) O[i][c] *= alpha;
#pragma unroll
                for (int j = 0; j < 4; j++)
                    Ps[(tx * 4 + j) * SPS + ty * 4 + i] = S[i][j];
            }
            __syncthreads();

            const float* __restrict__ vbase = g_v + ((size_t)b * NT + j0) * ND;
#pragma unroll
            for (int h = 0; h < 8; h++) {
                int sidx = tid + h * 256;
                int r = sidx >> 5;
                int c = (sidx & 31) * 4;
                *(float4*)&Vs[r * ND + c] = *(const float4*)&vbase[(size_t)r * ND + c];
            }
            __syncthreads();

#pragma unroll 2
            for (int j = 0; j < 64; j++) {
                float pp[4];
                pp[0] = Ps[j * SPS + ty * 4 + 0];
                pp[1] = Ps[j * SPS + ty * 4 + 1];
                pp[2] = Ps[j * SPS + ty * 4 + 2];
                pp[3] = Ps[j * SPS + ty * 4 + 3];
                float4 v0 = *(const float4*)&Vs[j * ND + tx * 8];
                float4 v1 = *(const float4*)&Vs[j * ND + tx * 8 + 4];
                float vv[8] = {v0.x, v0.y, v0.z, v0.w, v1.x, v1.y, v1.z, v1.w};
#pragma unroll
                for (int i = 0; i < 4; i++)
#pragma unroll
                    for (int c = 0; c < 8; c++)
                        O[i][c] += pp[i] * vv[c];
            }
        }

        float* __restrict__ obase = out + ((size_t)b * NT + q0) * ND;
#pragma unroll
        for (int i = 0; i < 4; i++) {
            float inv = 1.0f / l_i[i];
            float4 v0 = make_float4(O[i][0] * inv, O[i][1] * inv, O[i][2] * inv, O[i][3] * inv);
            float4 v1 = make_float4(O[i][4] * inv, O[i][5] * inv, O[i][6] * inv, O[i][7] * inv);
            *(float4*)&obase[(size_t)(ty * 4 + i) * ND + tx * 8] = v0;
            *(float4*)&obase[(size_t)(ty * 4 + i) * ND + tx * 8 + 4] = v1;
        }
        __syncthreads();  // protect smem reuse across passes
    }
}

// ---------------------------------------------------------------------------
extern "C" void kernel_launch(void* const* d_in, const int* in_sizes, int n_in,
                              void* d_out, int out_size)
{
    const float* x  = (const float*)d_in[0];
    const float* Wq = (const float*)d_in[1];
    const float* Wk = (const float*)d_in[2];
    const float* Wv = (const float*)d_in[3];
    float* out = (float*)d_out;

    const size_t attn_smem =
        (size_t)(128 * SQS + 128 * SQS + 64 * 128 + 64 * SPS) * sizeof(float);
    cudaFuncSetAttribute(attn_kernel, cudaFuncAttributeMaxDynamicSharedMemorySize,
                         (int)attn_smem);
    cudaFuncSetAttribute(proj_mma_kernel, cudaFuncAttributeMaxDynamicSharedMemorySize,
                         NSTAGE * STAGEB);

    split_x_kernel<<<(size_t)NM * NC / 8 / 256, 256>>>(x);
    split_w_kernel<<<dim3(NC * ND / 256, 3), 256>>>(Wq, Wk, Wv);

    dim3 pgrid(NM / 128, 1, 3);
    proj_mma_kernel<<<pgrid, 256, NSTAGE * STAGEB>>>();

    dim3 agrid(32, NB);
    attn_kernel<<<agrid, 256, attn_smem>>>(out);
}

// round 6
// speedup vs baseline: 2.7193x; 1.6140x over previous
#include <cuda_runtime.h>
#include <cuda_bf16.h>
#include <math_constants.h>
#include <cstdint>

#define NB 4
#define NT 4096
#define NC 2048
#define ND 128
#define NM (NB * NT)

// scale/log2e folded into Q at projection time: S comes out in log2 domain
#define QSC (0.08838834764831845f * 1.4426950408889634f)

// ---------------------------------------------------------------------------
// Scratch (device globals: allocation-free per harness rules)
// ---------------------------------------------------------------------------
__device__ __nv_bfloat16 g_xh[(size_t)NM * NC];   // x split hi  [M][K]
__device__ __nv_bfloat16 g_xl[(size_t)NM * NC];   // x split lo  [M][K]
__device__ __nv_bfloat16 g_wh[3 * ND * NC];       // W^T split hi [z][N][K]
__device__ __nv_bfloat16 g_wl[3 * ND * NC];       // W^T split lo [z][N][K]

__device__ __nv_bfloat16 g_qh[(size_t)NM * ND];   // [B][T][D] (pre-scaled)
__device__ __nv_bfloat16 g_ql[(size_t)NM * ND];
__device__ __nv_bfloat16 g_kh[(size_t)NM * ND];   // [B][T][D]
__device__ __nv_bfloat16 g_kl[(size_t)NM * ND];
__device__ __nv_bfloat16 g_vh[(size_t)NM * ND];   // [B][D][T] transposed
__device__ __nv_bfloat16 g_vl[(size_t)NM * ND];

// ---------------------------------------------------------------------------
// sm_80+ PTX helpers (harness targets sm_100: NO tcgen05/sm_100a-only ops)
// ---------------------------------------------------------------------------
__device__ __forceinline__ uint32_t smem_u32(const void* p) {
    uint32_t a;
    asm("{ .reg .u64 t; cvta.to.shared.u64 t, %1; cvt.u32.u64 %0, t; }"
        : "=r"(a) : "l"(p));
    return a;
}

__device__ __forceinline__ void ldsm_x4(uint32_t* r, uint32_t addr) {
    asm volatile("ldmatrix.sync.aligned.m8n8.x4.shared.b16 {%0,%1,%2,%3}, [%4];"
                 : "=r"(r[0]), "=r"(r[1]), "=r"(r[2]), "=r"(r[3])
                 : "r"(addr));
}

__device__ __forceinline__ void mma_bf16(float* c, const uint32_t* a,
                                         const uint32_t* b) {
    asm volatile(
        "mma.sync.aligned.m16n8k16.row.col.f32.bf16.bf16.f32 "
        "{%0,%1,%2,%3}, {%4,%5,%6,%7}, {%8,%9}, {%0,%1,%2,%3};"
        : "+f"(c[0]), "+f"(c[1]), "+f"(c[2]), "+f"(c[3])
        : "r"(a[0]), "r"(a[1]), "r"(a[2]), "r"(a[3]), "r"(b[0]), "r"(b[1]));
}

#define CP_ASYNC16(smem_addr, gptr) \
    asm volatile("cp.async.cg.shared.global [%0], [%1], 16;" \
                 :: "r"(smem_addr), "l"(gptr) : "memory")
#define CP_COMMIT() asm volatile("cp.async.commit_group;" ::: "memory")
#define CP_WAIT1()  asm volatile("cp.async.wait_group 1;" ::: "memory")
#define CP_WAIT0()  asm volatile("cp.async.wait_group 0;" ::: "memory")

__device__ __forceinline__ uint32_t pack_bf16x2_h(__nv_bfloat16 lo, __nv_bfloat16 hi) {
    __nv_bfloat162 t = __halves2bfloat162(lo, hi);   // .x = lo (low 16 bits)
    return *reinterpret_cast<uint32_t*>(&t);
}
__device__ __forceinline__ uint32_t pack_bf16x2_f(float lo, float hi) {
    uint32_t u;
    asm("cvt.rn.bf16x2.f32 %0, %1, %2;" : "=r"(u) : "f"(hi), "f"(lo));
    return u;
}

// 2^y on the FMA pipe (y <= 0). Safe under fast-math (explicit F2I/I2F).
__device__ __forceinline__ float exp2p(float y) {
    y = fmaxf(y, -100.f);
    int n = __float2int_rn(y);
    float f = y - __int2float_rn(n);       // f in [-0.5, 0.5]
    float p =          1.3333558e-3f;
    p = fmaf(p, f, 9.6181291e-3f);
    p = fmaf(p, f, 5.5504109e-2f);
    p = fmaf(p, f, 2.4022651e-1f);
    p = fmaf(p, f, 6.9314718e-1f);
    p = fmaf(p, f, 1.0f);
    return p * __int_as_float((127 + n) << 23);
}

// ---------------------------------------------------------------------------
// Prep: split fp32 -> hi/lo bf16 (x row-major; W transposed to [N][K])
// ---------------------------------------------------------------------------
__global__ __launch_bounds__(256) void split_x_kernel(const float* __restrict__ x) {
    size_t i = ((size_t)blockIdx.x * 256 + threadIdx.x) * 8;
    float4 a = *(const float4*)(x + i);
    float4 b = *(const float4*)(x + i + 4);
    float v[8] = {a.x, a.y, a.z, a.w, b.x, b.y, b.z, b.w};
    __nv_bfloat16 h[8], l[8];
#pragma unroll
    for (int j = 0; j < 8; j++) {
        h[j] = __float2bfloat16(v[j]);
        l[j] = __float2bfloat16(v[j] - __bfloat162float(h[j]));
    }
    *(uint4*)(g_xh + i) = *(const uint4*)h;
    *(uint4*)(g_xl + i) = *(const uint4*)l;
}

__global__ __launch_bounds__(256) void split_w_kernel(
    const float* __restrict__ Wq, const float* __restrict__ Wk,
    const float* __restrict__ Wv) {
    const int z = blockIdx.y;
    const float* __restrict__ W = (z == 0) ? Wq : (z == 1) ? Wk : Wv;
    int idx = blockIdx.x * 256 + threadIdx.x;
    int k = idx & (NC - 1);
    int n = idx >> 11;
    float v = W[(size_t)k * ND + n];
    __nv_bfloat16 h = __float2bfloat16(v);
    __nv_bfloat16 l = __float2bfloat16(v - __bfloat162float(h));
    size_t o = (size_t)z * ND * NC + (size_t)n * NC + k;
    g_wh[o] = h;
    g_wl[o] = l;
}

// ---------------------------------------------------------------------------
// Projection via mma.sync: C[128x128] = X @ W, split-bf16 (hh + lh + hl).
// Epilogue emits split-bf16 Q (scaled), K, V (V transposed to [B][D][T]).
// ---------------------------------------------------------------------------
#define KC 32
#define ROWB 80
#define MATB (128 * ROWB)
#define STAGEB (4 * MATB)
#define NSTAGE 3
#define NCHUNK (NC / KC)

__global__ __launch_bounds__(256) void proj_mma_kernel() {
    extern __shared__ char psm[];
    const uint32_t sb = smem_u32(psm);
    const int tid = threadIdx.x;
    const int w = tid >> 5;
    const int l = tid & 31;
    const int z = blockIdx.z;
    const int m0 = blockIdx.x * 128;

    const char* gb0 = (const char*)(g_xh + (size_t)m0 * NC);
    const char* gb1 = (const char*)(g_xl + (size_t)m0 * NC);
    const char* gb2 = (const char*)(g_wh + (size_t)z * ND * NC);
    const char* gb3 = (const char*)(g_wl + (size_t)z * ND * NC);

    auto load_stage = [&](int st, int c) {
        const size_t k0b = (size_t)c * (KC * 2);
        const char* gb[4] = {gb0 + k0b, gb1 + k0b, gb2 + k0b, gb3 + k0b};
#pragma unroll
        for (int m = 0; m < 4; m++) {
#pragma unroll
            for (int it = 0; it < 2; it++) {
                int q = it * 256 + tid;
                int r = q >> 2;
                int seg = q & 3;
                uint32_t s = sb + st * STAGEB + m * MATB + r * ROWB + seg * 16;
                const char* g = gb[m] + (size_t)r * (NC * 2) + seg * 16;
                CP_ASYNC16(s, g);
            }
        }
    };

    load_stage(0, 0); CP_COMMIT();
    load_stage(1, 1); CP_COMMIT();

    float acc[16][4] = {};

    for (int c = 0; c < NCHUNK; c++) {
        const int st = c % NSTAGE;
        if (c == NCHUNK - 1) { CP_WAIT0(); } else { CP_WAIT1(); }
        __syncthreads();
        if (c + 2 < NCHUNK) { load_stage((c + 2) % NSTAGE, c + 2); CP_COMMIT(); }

        const uint32_t stb = sb + st * STAGEB;
        const uint32_t abase = stb + (w * 16 + (l & 15)) * ROWB + (l >> 4) * 16;
        const uint32_t brow = (l & 7) + ((l >> 4) & 1) * 8;
        const uint32_t bsegl = ((l >> 3) & 1) * 16;

#pragma unroll
        for (int kk = 0; kk < 2; kk++) {
            uint32_t Ah[4], Al[4];
            ldsm_x4(Ah, abase + kk * 32);
            ldsm_x4(Al, abase + kk * 32 + MATB);
#pragma unroll
            for (int jp = 0; jp < 8; jp++) {
                uint32_t bo = stb + 2 * MATB + (16 * jp + brow) * ROWB +
                              kk * 32 + bsegl;
                uint32_t Bh[4], Bl[4];
                ldsm_x4(Bh, bo);
                ldsm_x4(Bl, bo + MATB);
                float* c0 = acc[2 * jp];
                float* c1 = acc[2 * jp + 1];
                mma_bf16(c0, Ah, Bh);     mma_bf16(c1, Ah, Bh + 2);
                mma_bf16(c0, Al, Bh);     mma_bf16(c1, Al, Bh + 2);
                mma_bf16(c0, Ah, Bl);     mma_bf16(c1, Ah, Bl + 2);
            }
        }
    }

    // Epilogue: split-bf16 outputs. acc[j][0..1]->row g cols 8j+2t,+1; [2..3]->row g+8
    const int g = l >> 2;
    const int t2 = (l & 3) * 2;
    const int row0 = m0 + w * 16 + g;
    const int bb = row0 >> 12;
    const int t0 = row0 & (NT - 1);

    if (z != 2) {
        __nv_bfloat16* gh = (z == 0) ? g_qh : g_kh;
        __nv_bfloat16* gl = (z == 0) ? g_ql : g_kl;
        const float sc = (z == 0) ? QSC : 1.0f;
#pragma unroll
        for (int j = 0; j < 16; j++) {
            int col = 8 * j + t2;
#pragma unroll
            for (int rr = 0; rr < 2; rr++) {
                float v0 = acc[j][2 * rr] * sc;
                float v1 = acc[j][2 * rr + 1] * sc;
                __nv_bfloat16 h0 = __float2bfloat16(v0);
                __nv_bfloat16 h1 = __float2bfloat16(v1);
                float l0 = v0 - __bfloat162float(h0);
                float l1 = v1 - __bfloat162float(h1);
                size_t o = (size_t)(row0 + rr * 8) * ND + col;
                *(uint32_t*)&gh[o] = pack_bf16x2_h(h0, h1);
                *(uint32_t*)&gl[o] = pack_bf16x2_f(l0, l1);
            }
        }
    } else {
        // V transposed: [B][D][T]
#pragma unroll
        for (int j = 0; j < 16; j++) {
#pragma unroll
            for (int e = 0; e < 2; e++) {
                int col = 8 * j + t2 + e;
#pragma unroll
                for (int rr = 0; rr < 2; rr++) {
                    float v = acc[j][2 * rr + e];
                    __nv_bfloat16 h = __float2bfloat16(v);
                    float lo = v - __bfloat162float(h);
                    size_t o = (size_t)(bb * ND + col) * NT + t0 + rr * 8;
                    g_vh[o] = h;
                    g_vl[o] = __float2bfloat16(lo);
                }
            }
        }
    }
}

// ---------------------------------------------------------------------------
// HMMA flash attention. BQ=128, BKV=64, 256 threads (8 warps, warp=m16).
// S = QhKh + QlKh + QhKl (log2 domain, scale pre-folded into Q).
// O += PhVh + PlVh + PhVl.  2-stage cp.async KV pipeline.
// ---------------------------------------------------------------------------
#define QROW 272
#define QMAT (128 * QROW)          // 34816 (Qh->Ql offset)
#define SM_QH 0
#define SM_K  (2 * QMAT)           // 69632
#define KROW 272
#define KMAT (64 * KROW)           // 17408 (Kh->Kl offset)
#define KSTG (2 * KMAT)            // 34816
#define SM_V  (SM_K + 2 * KSTG)    // 139264
#define VROW 144
#define VMAT (128 * VROW)          // 18432 (Vh->Vl offset)
#define VSTG (2 * VMAT)            // 36864
#define ATTN_SMEM (SM_V + 2 * VSTG) // 212992

__global__ __launch_bounds__(256, 1) void attn_mma_kernel(float* __restrict__ out)
{
    extern __shared__ char sbuf[];
    const uint32_t sb = smem_u32(sbuf);
    const int tid = threadIdx.x;
    const int w = tid >> 5, l = tid & 31;
    const int qb = blockIdx.x, b = blockIdx.y;
    const int q0 = qb * 128;

    // Q tile (loaded once)
    {
        const char* qh = (const char*)(g_qh + (size_t)(b * NT + q0) * ND);
        const char* ql = (const char*)(g_ql + (size_t)(b * NT + q0) * ND);
#pragma unroll
        for (int it = 0; it < 8; it++) {
            int idx = it * 256 + tid;
            int r = idx >> 4, sg = idx & 15;
            CP_ASYNC16(sb + SM_QH + r * QROW + sg * 16, qh + (size_t)r * 256 + sg * 16);
            CP_ASYNC16(sb + SM_QH + QMAT + r * QROW + sg * 16, ql + (size_t)r * 256 + sg * 16);
        }
    }

    auto load_kv = [&](int jt, int stg) {
        const int j0 = jt * 64;
        const char* kh = (const char*)(g_kh + (size_t)(b * NT + j0) * ND);
        const char* kl = (const char*)(g_kl + (size_t)(b * NT + j0) * ND);
        const uint32_t kb = sb + SM_K + stg * KSTG;
#pragma unroll
        for (int it = 0; it < 4; it++) {
            int idx = it * 256 + tid;
            int r = idx >> 4, sg = idx & 15;
            CP_ASYNC16(kb + r * KROW + sg * 16, kh + (size_t)r * 256 + sg * 16);
            CP_ASYNC16(kb + KMAT + r * KROW + sg * 16, kl + (size_t)r * 256 + sg * 16);
        }
        const char* vhB = (const char*)g_vh;
        const char* vlB = (const char*)g_vl;
        const uint32_t vb = sb + SM_V + stg * VSTG;
#pragma unroll
        for (int it = 0; it < 4; it++) {
            int idx = it * 256 + tid;
            int d = idx >> 3, sg = idx & 7;
            size_t go = ((size_t)(b * ND + d) * NT + j0) * 2 + sg * 16;
            CP_ASYNC16(vb + d * VROW + sg * 16, vhB + go);
            CP_ASYNC16(vb + VMAT + d * VROW + sg * 16, vlB + go);
        }
    };

    load_kv(0, 0);
    CP_COMMIT();                       // one group: Q + KV tile 0

    float O[16][4] = {};
    float mrow0 = -CUDART_INF_F, mrow1 = -CUDART_INF_F;
    float lrow0 = 0.f, lrow1 = 0.f;

    const int g = l >> 2;
    const int t2 = (l & 3) * 2;
    const int row0 = q0 + w * 16 + g;
    const int row1 = row0 + 8;
    const uint32_t brow = (l & 7) + ((l >> 4) & 1) * 8;
    const uint32_t bseg = ((l >> 3) & 1) * 16;
    const uint32_t qa = sb + SM_QH + (w * 16 + (l & 15)) * QROW + (l >> 4) * 16;

    const int ntiles = 2 * qb + 2;
    for (int jt = 0; jt < ntiles; jt++) {
        const int stg = jt & 1;
        if (jt + 1 < ntiles) { load_kv(jt + 1, (jt + 1) & 1); CP_COMMIT(); CP_WAIT1(); }
        else { CP_WAIT0(); }
        __syncthreads();

        // ---- S = Q K^T ----
        float S[8][4];
#pragma unroll
        for (int f = 0; f < 8; f++) { S[f][0] = S[f][1] = S[f][2] = S[f][3] = 0.f; }
        const uint32_t kb = sb + SM_K + stg * KSTG;
#pragma unroll
        for (int kk = 0; kk < 8; kk++) {
            uint32_t Ah[4], Al[4];
            ldsm_x4(Ah, qa + kk * 32);
            ldsm_x4(Al, qa + QMAT + kk * 32);
#pragma unroll
            for (int jp = 0; jp < 4; jp++) {
                uint32_t bo = kb + (jp * 16 + brow) * KROW + kk * 32 + bseg;
                uint32_t Bh[4], Bl[4];
                ldsm_x4(Bh, bo);
                ldsm_x4(Bl, bo + KMAT);
                mma_bf16(S[2 * jp], Ah, Bh);  mma_bf16(S[2 * jp + 1], Ah, Bh + 2);
                mma_bf16(S[2 * jp], Al, Bh);  mma_bf16(S[2 * jp + 1], Al, Bh + 2);
                mma_bf16(S[2 * jp], Ah, Bl);  mma_bf16(S[2 * jp + 1], Ah, Bl + 2);
            }
        }

        // ---- causal mask (only last two tiles need it) ----
        const int j0 = jt * 64;
        if (jt >= 2 * qb) {
#pragma unroll
            for (int f = 0; f < 8; f++) {
                int c0 = j0 + 8 * f + t2;
                if (c0     > row0) S[f][0] = -CUDART_INF_F;
                if (c0 + 1 > row0) S[f][1] = -CUDART_INF_F;
                if (c0     > row1) S[f][2] = -CUDART_INF_F;
                if (c0 + 1 > row1) S[f][3] = -CUDART_INF_F;
            }
        }

        // ---- online softmax (log2 domain) ----
        float mt0 = -CUDART_INF_F, mt1 = -CUDART_INF_F;
#pragma unroll
        for (int f = 0; f < 8; f++) {
            mt0 = fmaxf(mt0, fmaxf(S[f][0], S[f][1]));
            mt1 = fmaxf(mt1, fmaxf(S[f][2], S[f][3]));
        }
        mt0 = fmaxf(mt0, __shfl_xor_sync(0xffffffffu, mt0, 1));
        mt0 = fmaxf(mt0, __shfl_xor_sync(0xffffffffu, mt0, 2));
        mt1 = fmaxf(mt1, __shfl_xor_sync(0xffffffffu, mt1, 1));
        mt1 = fmaxf(mt1, __shfl_xor_sync(0xffffffffu, mt1, 2));
        const float mn0 = fmaxf(mrow0, mt0);
        const float mn1 = fmaxf(mrow1, mt1);
        const float a0 = exp2p(mrow0 - mn0);
        const float a1 = exp2p(mrow1 - mn1);
        mrow0 = mn0; mrow1 = mn1;

        uint32_t Pah[4][4], Pal[4][4];
        float ls0 = 0.f, ls1 = 0.f;
#pragma unroll
        for (int f = 0; f < 8; f++) {
            float p0 = exp2p(S[f][0] - mn0);
            float p1 = exp2p(S[f][1] - mn0);
            float p2 = exp2p(S[f][2] - mn1);
            float p3 = exp2p(S[f][3] - mn1);
            ls0 += p0 + p1; ls1 += p2 + p3;
            __nv_bfloat16 h0 = __float2bfloat16(p0), h1 = __float2bfloat16(p1);
            __nv_bfloat16 h2 = __float2bfloat16(p2), h3 = __float2bfloat16(p3);
            float e0 = p0 - __bfloat162float(h0), e1 = p1 - __bfloat162float(h1);
            float e2 = p2 - __bfloat162float(h2), e3 = p3 - __bfloat162float(h3);
            int ks = f >> 1, hi = (f & 1) * 2;
            Pah[ks][hi]     = pack_bf16x2_h(h0, h1);
            Pah[ks][hi + 1] = pack_bf16x2_h(h2, h3);
            Pal[ks][hi]     = pack_bf16x2_f(e0, e1);
            Pal[ks][hi + 1] = pack_bf16x2_f(e2, e3);
        }
        lrow0 = lrow0 * a0 + ls0;
        lrow1 = lrow1 * a1 + ls1;
#pragma unroll
        for (int f = 0; f < 16; f++) {
            O[f][0] *= a0; O[f][1] *= a0; O[f][2] *= a1; O[f][3] *= a1;
        }

        // ---- O += P V ----
        const uint32_t vb = sb + SM_V + stg * VSTG;
#pragma unroll
        for (int nn = 0; nn < 8; nn++) {
#pragma unroll
            for (int ks = 0; ks < 4; ks++) {
                uint32_t vo = vb + (nn * 16 + brow) * VROW + ks * 32 + bseg;
                uint32_t Vh[4], Vl[4];
                ldsm_x4(Vh, vo);
                ldsm_x4(Vl, vo + VMAT);
                mma_bf16(O[2 * nn], Pah[ks], Vh);  mma_bf16(O[2 * nn + 1], Pah[ks], Vh + 2);
                mma_bf16(O[2 * nn], Pal[ks], Vh);  mma_bf16(O[2 * nn + 1], Pal[ks], Vh + 2);
                mma_bf16(O[2 * nn], Pah[ks], Vl);  mma_bf16(O[2 * nn + 1], Pah[ks], Vl + 2);
            }
        }
        __syncthreads();  // done with stage stg before it is refilled
    }

    // ---- epilogue ----
    lrow0 += __shfl_xor_sync(0xffffffffu, lrow0, 1);
    lrow0 += __shfl_xor_sync(0xffffffffu, lrow0, 2);
    lrow1 += __shfl_xor_sync(0xffffffffu, lrow1, 1);
    lrow1 += __shfl_xor_sync(0xffffffffu, lrow1, 2);
    const float i0 = 1.f / lrow0, i1 = 1.f / lrow1;
    float* ob0 = out + ((size_t)b * NT + row0) * ND;
    float* ob1 = out + ((size_t)b * NT + row1) * ND;
#pragma unroll
    for (int f = 0; f < 16; f++) {
        int col = 8 * f + t2;
        *(float2*)&ob0[col] = make_float2(O[f][0] * i0, O[f][1] * i0);
        *(float2*)&ob1[col] = make_float2(O[f][2] * i1, O[f][3] * i1);
    }
}

// ---------------------------------------------------------------------------
extern "C" void kernel_launch(void* const* d_in, const int* in_sizes, int n_in,
                              void* d_out, int out_size)
{
    const float* x  = (const float*)d_in[0];
    const float* Wq = (const float*)d_in[1];
    const float* Wk = (const float*)d_in[2];
    const float* Wv = (const float*)d_in[3];
    float* out = (float*)d_out;

    cudaFuncSetAttribute(proj_mma_kernel, cudaFuncAttributeMaxDynamicSharedMemorySize,
                         NSTAGE * STAGEB);
    cudaFuncSetAttribute(attn_mma_kernel, cudaFuncAttributeMaxDynamicSharedMemorySize,
                         ATTN_SMEM);

    split_x_kernel<<<(size_t)NM * NC / 8 / 256, 256>>>(x);
    split_w_kernel<<<dim3(NC * ND / 256, 3), 256>>>(Wq, Wk, Wv);

    dim3 pgrid(NM / 128, 1, 3);
    proj_mma_kernel<<<pgrid, 256, NSTAGE * STAGEB>>>();

    dim3 agrid(NT / 128, NB);
    attn_mma_kernel<<<agrid, 256, ATTN_SMEM>>>(out);
}